// round 7
// baseline (speedup 1.0000x reference)
#include <cuda_runtime.h>
#include <math.h>

#define BATCH  4096
#define NPATCH 196

// Folded head weights as float4: g_W2[(k*196+m)*4 + d] = W2[k][4m+d]
__device__ __align__(16) float g_W2[10 * 784];
// Bilinear coefficient matrices (flattened [4][9]); e_w = u(a)^T A_w u(a'),
// u = (1, cos a, sin a). w=0,1 over (a0,a1); w=2,3 over (a2,a3).
__device__ float g_A[36];

// ---------------------------------------------------------------------------
// Per-thread probe: given half-angle amplitudes (chi,shi),(chj,shj) for the
// two encoder wires of a subsystem, run the fixed 2-qubit circuit twice
// (subsystem A: RX(q0),RY(q1),CNOT,RY(q4); subsystem B: RZ(q2),RX(q3),CNOT,RZ(q5))
// and return the 4 Pauli-Z probe values F[w].
// ---------------------------------------------------------------------------
__device__ __forceinline__ void probe_circuit(float chi, float shi, float chj, float shj,
                                              const float* qc, const float* qs,
                                              float F[4]) {
    // ---- subsystem A: wires 0 (high bit), 1 (low bit) ----
    {
        float re[4], im[4];
        re[0] = chi * chj; re[1] = chi * shj;
        re[2] = shi * chj; re[3] = shi * shj;
        im[0] = im[1] = im[2] = im[3] = 0.0f;
        // RX(q0) on high bit: pairs (0,2),(1,3)
        #pragma unroll
        for (int b = 0; b < 2; b++) {
            int a = b, t = b | 2;
            float ra = re[a], ia = im[a], rb = re[t], ib = im[t];
            float c = qc[0], s = qs[0];
            re[a] = c * ra + s * ib;  im[a] = c * ia - s * rb;
            re[t] = s * ia + c * rb;  im[t] = -s * ra + c * ib;
        }
        // RY(q1) on low bit: pairs (0,1),(2,3)
        #pragma unroll
        for (int b = 0; b < 4; b += 2) {
            int a = b, t = b | 1;
            float ra = re[a], ia = im[a], rb = re[t], ib = im[t];
            float c = qc[1], s = qs[1];
            re[a] = c * ra - s * rb;  im[a] = c * ia - s * ib;
            re[t] = s * ra + c * rb;  im[t] = s * ia + c * ib;
        }
        // CNOT(high->low): swap 2<->3
        { float t0 = re[2]; re[2] = re[3]; re[3] = t0;
          float t1 = im[2]; im[2] = im[3]; im[3] = t1; }
        // RY(q4) on high bit
        #pragma unroll
        for (int b = 0; b < 2; b++) {
            int a = b, t = b | 2;
            float ra = re[a], ia = im[a], rb = re[t], ib = im[t];
            float c = qc[4], s = qs[4];
            re[a] = c * ra - s * rb;  im[a] = c * ia - s * ib;
            re[t] = s * ra + c * rb;  im[t] = s * ia + c * ib;
        }
        float p0 = re[0]*re[0]+im[0]*im[0], p1 = re[1]*re[1]+im[1]*im[1];
        float p2 = re[2]*re[2]+im[2]*im[2], p3 = re[3]*re[3]+im[3]*im[3];
        F[0] = p0 + p1 - p2 - p3;
        F[1] = p0 - p1 + p2 - p3;
    }
    // ---- subsystem B: wires 2 (high bit), 3 (low bit) ----
    {
        float re[4], im[4];
        re[0] = chi * chj; re[1] = chi * shj;
        re[2] = shi * chj; re[3] = shi * shj;
        im[0] = im[1] = im[2] = im[3] = 0.0f;
        // RZ(q2) on high
        #pragma unroll
        for (int a = 0; a < 4; a++) {
            float c = qc[2], s = (a & 2) ? -qs[2] : qs[2];
            float ra = re[a], ia = im[a];
            re[a] = c * ra + s * ia;  im[a] = c * ia - s * ra;
        }
        // RX(q3) on low bit
        #pragma unroll
        for (int b = 0; b < 4; b += 2) {
            int a = b, t = b | 1;
            float ra = re[a], ia = im[a], rb = re[t], ib = im[t];
            float c = qc[3], s = qs[3];
            re[a] = c * ra + s * ib;  im[a] = c * ia - s * rb;
            re[t] = s * ia + c * rb;  im[t] = -s * ra + c * ib;
        }
        // CNOT(high->low): swap 2<->3
        { float t0 = re[2]; re[2] = re[3]; re[3] = t0;
          float t1 = im[2]; im[2] = im[3]; im[3] = t1; }
        // RZ(q5) on low
        #pragma unroll
        for (int a = 0; a < 4; a++) {
            float c = qc[5], s = (a & 1) ? -qs[5] : qs[5];
            float ra = re[a], ia = im[a];
            re[a] = c * ra + s * ia;  im[a] = c * ia - s * ra;
        }
        float p0 = re[0]*re[0]+im[0]*im[0], p1 = re[1]*re[1]+im[1]*im[1];
        float p2 = re[2]*re[2]+im[2]*im[2], p3 = re[3]*re[3]+im[3]*im[3];
        F[2] = p0 + p1 - p2 - p3;
        F[3] = p0 - p1 + p2 - p3;
    }
}

// Cooperative coefficient build: threads 0..8 probe, threads 0..3 convert.
// Leaves sA[36] populated. Requires one __syncthreads between phases (done
// by the caller pattern below).
__device__ __forceinline__ void build_A_phase1(const float* __restrict__ qp,
                                               float* sF /*[4*9]*/, int tid) {
    if (tid < 9) {
        float qc[6], qs[6];
        #pragma unroll
        for (int k = 0; k < 6; k++) sincosf(0.5f * __ldg(&qp[k]), &qs[k], &qc[k]);
        const float chp[3] = {1.0f, 0.7071067811865476f, 0.0f};
        const float shp[3] = {0.0f, 0.7071067811865476f, 1.0f};
        int i = tid / 3, j = tid - 3 * i;
        float F[4];
        probe_circuit(chp[i], shp[i], chp[j], shp[j], qc, qs, F);
        #pragma unroll
        for (int w = 0; w < 4; w++) sF[w * 9 + tid] = F[w];
    }
}

__device__ __forceinline__ void build_A_phase2(const float* sF, float* sA, int tid) {
    if (tid < 4) {
        const int w = tid;
        float G[3][3];
        #pragma unroll
        for (int j = 0; j < 3; j++) {
            float f0 = sF[w * 9 + 0 * 3 + j];
            float f1 = sF[w * 9 + 1 * 3 + j];
            float f2 = sF[w * 9 + 2 * 3 + j];
            float p = 0.5f * (f0 + f2);
            G[0][j] = p; G[1][j] = 0.5f * (f0 - f2); G[2][j] = f1 - p;
        }
        #pragma unroll
        for (int i = 0; i < 3; i++) {
            float p = 0.5f * (G[i][0] + G[i][2]);
            sA[w * 9 + i * 3 + 0] = p;
            sA[w * 9 + i * 3 + 1] = 0.5f * (G[i][0] - G[i][2]);
            sA[w * 9 + i * 3 + 2] = G[i][1] - p;
        }
    }
}

// ---------------------------------------------------------------------------
// Per-patch measurement: 4 fast sincos + 32 FMA
// ---------------------------------------------------------------------------
__device__ __forceinline__ float4 measure4(float a0, float a1, float a2, float a3,
                                           const float* __restrict__ A) {
    float c0, s0, c1, s1, c2, s2, c3, s3;
    __sincosf(a0, &s0, &c0);
    __sincosf(a1, &s1, &c1);
    __sincosf(a2, &s2, &c2);
    __sincosf(a3, &s3, &c3);
    float4 e;
    {
        const float* B = A;
        float t0 = fmaf(B[2], s1, fmaf(B[1], c1, B[0]));
        float t1 = fmaf(B[5], s1, fmaf(B[4], c1, B[3]));
        float t2 = fmaf(B[8], s1, fmaf(B[7], c1, B[6]));
        e.x = fmaf(s0, t2, fmaf(c0, t1, t0));
    }
    {
        const float* B = A + 9;
        float t0 = fmaf(B[2], s1, fmaf(B[1], c1, B[0]));
        float t1 = fmaf(B[5], s1, fmaf(B[4], c1, B[3]));
        float t2 = fmaf(B[8], s1, fmaf(B[7], c1, B[6]));
        e.y = fmaf(s0, t2, fmaf(c0, t1, t0));
    }
    {
        const float* B = A + 18;
        float t0 = fmaf(B[2], s3, fmaf(B[1], c3, B[0]));
        float t1 = fmaf(B[5], s3, fmaf(B[4], c3, B[3]));
        float t2 = fmaf(B[8], s3, fmaf(B[7], c3, B[6]));
        e.z = fmaf(s2, t2, fmaf(c2, t1, t0));
    }
    {
        const float* B = A + 27;
        float t0 = fmaf(B[2], s3, fmaf(B[1], c3, B[0]));
        float t1 = fmaf(B[5], s3, fmaf(B[4], c3, B[3]));
        float t2 = fmaf(B[8], s3, fmaf(B[7], c3, B[6]));
        e.w = fmaf(s2, t2, fmaf(c2, t1, t0));
    }
    return e;
}

// ---------------------------------------------------------------------------
// K1: coefficients (in-block) + sample-0 measure -> adjacency -> W2 fold.
// One block per m (196 blocks), 256 threads. Block 0 also publishes g_A.
// ---------------------------------------------------------------------------
__global__ void __launch_bounds__(256) fold_kernel(const float* __restrict__ x,
                                                   const float* __restrict__ qp,
                                                   const float* __restrict__ W) {
    __shared__ float sF[36];
    __shared__ float sA[36];
    __shared__ float v[196][4];
    __shared__ float nrm[196];
    __shared__ float adjc[196];

    const int m   = blockIdx.x;
    const int tid = threadIdx.x;

    build_A_phase1(qp, sF, tid);
    __syncthreads();
    build_A_phase2(sF, sA, tid);
    __syncthreads();

    if (blockIdx.x == 0 && tid < 36) g_A[tid] = sA[tid];

    if (tid < 196) {
        int pi = tid / 14, pj = tid - pi * 14;
        const float* xb = x + (2 * pi) * 28 + 2 * pj;
        float4 e = measure4(xb[0], xb[1], xb[28], xb[29], sA);
        v[tid][0] = e.x; v[tid][1] = e.y; v[tid][2] = e.z; v[tid][3] = e.w;
        nrm[tid] = sqrtf(e.x * e.x + e.y * e.y + e.z * e.z + e.w * e.w);
    }
    __syncthreads();

    if (tid < 196) {
        float dot = v[tid][0] * v[m][0] + v[tid][1] * v[m][1] +
                    v[tid][2] * v[m][2] + v[tid][3] * v[m][3];
        float sim = dot / (nrm[tid] * nrm[m] + 1e-12f);
        adjc[tid] = (sim >= 0.9f) ? 1.0f : ((sim >= 0.5f) ? 0.5f : 0.0f);
    }
    __syncthreads();

    // W2[k][4m+d] = sum_n adj[n,m] * W[k][4n+d]; 40 outputs, 5 per warp,
    // lane-strided dot + shfl reduce.
    const int warp = tid >> 5;
    const int lane = tid & 31;
    #pragma unroll
    for (int q = 0; q < 5; q++) {
        const int o = warp * 5 + q;
        const int k = o >> 2, d = o & 3;
        float s = 0.0f;
        #pragma unroll
        for (int n = lane; n < 196; n += 32)
            s = fmaf(adjc[n], __ldg(&W[k * 784 + 4 * n + d]), s);
        #pragma unroll
        for (int off = 16; off; off >>= 1)
            s += __shfl_xor_sync(0xFFFFFFFFu, s, off);
        if (lane == 0)
            g_W2[k * 784 + 4 * m + d] = s;
    }
}

// ---------------------------------------------------------------------------
// K2: fused main. One warp = TWO batch samples (W2 loads reused across both).
// 16 samples/block, 256 blocks. Lane 0 / lane 1 finalize the two samples.
// ---------------------------------------------------------------------------
#define SPB 16   // samples per block
__global__ void __launch_bounds__(256) main_kernel(const float* __restrict__ x,
                                                   const float* __restrict__ bias,
                                                   float* __restrict__ out) {
    __shared__ float sx[SPB * 784];   // 50176 B
    __shared__ float sA[36];

    const int tid  = threadIdx.x;
    const int warp = tid >> 5;
    const int lane = tid & 31;

    // cooperative vectorized stage of 16 sample rows
    {
        const float4* xin = (const float4*)(x + (size_t)blockIdx.x * SPB * 784);
        float4* sx4 = (float4*)sx;
        #pragma unroll
        for (int i = tid; i < SPB * 196; i += 256) sx4[i] = xin[i];
    }
    if (tid < 36) sA[tid] = g_A[tid];
    __syncthreads();

    float A[36];
    #pragma unroll
    for (int i = 0; i < 36; i++) A[i] = sA[i];

    const float* rowA = sx + (2 * warp) * 784;
    const float* rowB = rowA + 784;
    const float4* W2v = (const float4*)g_W2;   // [10][196]

    float accA[10], accB[10];
    #pragma unroll
    for (int k = 0; k < 10; k++) { accA[k] = 0.0f; accB[k] = 0.0f; }

    int m  = lane;
    int pi = lane / 14;
    int pj = lane - pi * 14;
    #pragma unroll
    for (int it = 0; it < 7; it++) {
        if (it < 6 || m < 196) {
            const int off = pi * 56 + 2 * pj;
            const float2 tA = *(const float2*)(rowA + off);
            const float2 bA = *(const float2*)(rowA + off + 28);
            const float2 tB = *(const float2*)(rowB + off);
            const float2 bB = *(const float2*)(rowB + off + 28);
            float4 eA = measure4(tA.x, tA.y, bA.x, bA.y, A);
            float4 eB = measure4(tB.x, tB.y, bB.x, bB.y, A);
            #pragma unroll
            for (int k = 0; k < 10; k++) {
                float4 w4 = __ldg(W2v + k * 196 + m);
                accA[k] = fmaf(eA.x, w4.x, fmaf(eA.y, w4.y,
                          fmaf(eA.z, w4.z, fmaf(eA.w, w4.w, accA[k]))));
                accB[k] = fmaf(eB.x, w4.x, fmaf(eB.y, w4.y,
                          fmaf(eB.z, w4.z, fmaf(eB.w, w4.w, accB[k]))));
            }
        }
        m += 32;
        pj += 4; pi += 2;
        if (pj >= 14) { pj -= 14; pi += 1; }
    }

    #pragma unroll
    for (int k = 0; k < 10; k++) {
        #pragma unroll
        for (int off = 16; off; off >>= 1) {
            accA[k] += __shfl_xor_sync(0xFFFFFFFFu, accA[k], off);
            accB[k] += __shfl_xor_sync(0xFFFFFFFFu, accB[k], off);
        }
    }

    if (lane < 2) {
        const int samp = blockIdx.x * SPB + 2 * warp + lane;
        float logit[10], mx2 = -1e30f;
        #pragma unroll
        for (int k = 0; k < 10; k++) {
            float a = (lane == 0) ? accA[k] : accB[k];
            logit[k] = a + __ldg(&bias[k]);
            mx2 = fmaxf(mx2, logit[k]);
        }
        float sum = 0.0f;
        #pragma unroll
        for (int k = 0; k < 10; k++) sum += __expf(logit[k] - mx2);
        float lse = mx2 + __logf(sum);
        #pragma unroll
        for (int k = 0; k < 10; k++)
            out[samp * 10 + k] = logit[k] - lse;
    }
}

extern "C" void kernel_launch(void* const* d_in, const int* in_sizes, int n_in,
                              void* d_out, int out_size) {
    const float* x  = (const float*)d_in[0];
    const float* qp = (const float*)d_in[1];
    const float* W  = (const float*)d_in[2];
    const float* b  = (const float*)d_in[3];
    float* out = (float*)d_out;

    fold_kernel<<<196, 256>>>(x, qp, W);
    main_kernel<<<BATCH / SPB, 256>>>(x, b, out);
}

// round 8
// speedup vs baseline: 1.2790x; 1.2790x over previous
#include <cuda_runtime.h>
#include <math.h>

#define BATCH  4096
#define NPATCH 196

// Folded head weights as float4: g_W2[(k*196+m)*4 + d] = W2[k][4m+d]
__device__ __align__(16) float g_W2[10 * 784];
// Bilinear coefficient matrices (flattened [4][9]); e_w = u(a)^T A_w u(a'),
// u = (1, cos a, sin a). w=0,1 over (a0,a1); w=2,3 over (a2,a3).
__device__ float g_A[36];

// ---------------------------------------------------------------------------
// Per-thread probe: given half-angle amplitudes (chi,shi),(chj,shj) for the
// two encoder wires of a subsystem, run the fixed 2-qubit circuit twice
// (subsystem A: RX(q0),RY(q1),CNOT,RY(q4); subsystem B: RZ(q2),RX(q3),CNOT,RZ(q5))
// and return the 4 Pauli-Z probe values F[w].
// ---------------------------------------------------------------------------
__device__ __forceinline__ void probe_circuit(float chi, float shi, float chj, float shj,
                                              const float* qc, const float* qs,
                                              float F[4]) {
    // ---- subsystem A: wires 0 (high bit), 1 (low bit) ----
    {
        float re[4], im[4];
        re[0] = chi * chj; re[1] = chi * shj;
        re[2] = shi * chj; re[3] = shi * shj;
        im[0] = im[1] = im[2] = im[3] = 0.0f;
        // RX(q0) on high bit: pairs (0,2),(1,3)
        #pragma unroll
        for (int b = 0; b < 2; b++) {
            int a = b, t = b | 2;
            float ra = re[a], ia = im[a], rb = re[t], ib = im[t];
            float c = qc[0], s = qs[0];
            re[a] = c * ra + s * ib;  im[a] = c * ia - s * rb;
            re[t] = s * ia + c * rb;  im[t] = -s * ra + c * ib;
        }
        // RY(q1) on low bit: pairs (0,1),(2,3)
        #pragma unroll
        for (int b = 0; b < 4; b += 2) {
            int a = b, t = b | 1;
            float ra = re[a], ia = im[a], rb = re[t], ib = im[t];
            float c = qc[1], s = qs[1];
            re[a] = c * ra - s * rb;  im[a] = c * ia - s * ib;
            re[t] = s * ra + c * rb;  im[t] = s * ia + c * ib;
        }
        // CNOT(high->low): swap 2<->3
        { float t0 = re[2]; re[2] = re[3]; re[3] = t0;
          float t1 = im[2]; im[2] = im[3]; im[3] = t1; }
        // RY(q4) on high bit
        #pragma unroll
        for (int b = 0; b < 2; b++) {
            int a = b, t = b | 2;
            float ra = re[a], ia = im[a], rb = re[t], ib = im[t];
            float c = qc[4], s = qs[4];
            re[a] = c * ra - s * rb;  im[a] = c * ia - s * ib;
            re[t] = s * ra + c * rb;  im[t] = s * ia + c * ib;
        }
        float p0 = re[0]*re[0]+im[0]*im[0], p1 = re[1]*re[1]+im[1]*im[1];
        float p2 = re[2]*re[2]+im[2]*im[2], p3 = re[3]*re[3]+im[3]*im[3];
        F[0] = p0 + p1 - p2 - p3;
        F[1] = p0 - p1 + p2 - p3;
    }
    // ---- subsystem B: wires 2 (high bit), 3 (low bit) ----
    {
        float re[4], im[4];
        re[0] = chi * chj; re[1] = chi * shj;
        re[2] = shi * chj; re[3] = shi * shj;
        im[0] = im[1] = im[2] = im[3] = 0.0f;
        // RZ(q2) on high
        #pragma unroll
        for (int a = 0; a < 4; a++) {
            float c = qc[2], s = (a & 2) ? -qs[2] : qs[2];
            float ra = re[a], ia = im[a];
            re[a] = c * ra + s * ia;  im[a] = c * ia - s * ra;
        }
        // RX(q3) on low bit
        #pragma unroll
        for (int b = 0; b < 4; b += 2) {
            int a = b, t = b | 1;
            float ra = re[a], ia = im[a], rb = re[t], ib = im[t];
            float c = qc[3], s = qs[3];
            re[a] = c * ra + s * ib;  im[a] = c * ia - s * rb;
            re[t] = s * ia + c * rb;  im[t] = -s * ra + c * ib;
        }
        // CNOT(high->low): swap 2<->3
        { float t0 = re[2]; re[2] = re[3]; re[3] = t0;
          float t1 = im[2]; im[2] = im[3]; im[3] = t1; }
        // RZ(q5) on low
        #pragma unroll
        for (int a = 0; a < 4; a++) {
            float c = qc[5], s = (a & 1) ? -qs[5] : qs[5];
            float ra = re[a], ia = im[a];
            re[a] = c * ra + s * ia;  im[a] = c * ia - s * ra;
        }
        float p0 = re[0]*re[0]+im[0]*im[0], p1 = re[1]*re[1]+im[1]*im[1];
        float p2 = re[2]*re[2]+im[2]*im[2], p3 = re[3]*re[3]+im[3]*im[3];
        F[2] = p0 + p1 - p2 - p3;
        F[3] = p0 - p1 + p2 - p3;
    }
}

// Cooperative coefficient build: threads 0..8 probe, threads 0..3 convert.
// Leaves sA[36] populated. Requires one __syncthreads between phases (done
// by the caller pattern below).
__device__ __forceinline__ void build_A_phase1(const float* __restrict__ qp,
                                               float* sF /*[4*9]*/, int tid) {
    if (tid < 9) {
        float qc[6], qs[6];
        #pragma unroll
        for (int k = 0; k < 6; k++) sincosf(0.5f * __ldg(&qp[k]), &qs[k], &qc[k]);
        const float chp[3] = {1.0f, 0.7071067811865476f, 0.0f};
        const float shp[3] = {0.0f, 0.7071067811865476f, 1.0f};
        int i = tid / 3, j = tid - 3 * i;
        float F[4];
        probe_circuit(chp[i], shp[i], chp[j], shp[j], qc, qs, F);
        #pragma unroll
        for (int w = 0; w < 4; w++) sF[w * 9 + tid] = F[w];
    }
}

__device__ __forceinline__ void build_A_phase2(const float* sF, float* sA, int tid) {
    if (tid < 4) {
        const int w = tid;
        float G[3][3];
        #pragma unroll
        for (int j = 0; j < 3; j++) {
            float f0 = sF[w * 9 + 0 * 3 + j];
            float f1 = sF[w * 9 + 1 * 3 + j];
            float f2 = sF[w * 9 + 2 * 3 + j];
            float p = 0.5f * (f0 + f2);
            G[0][j] = p; G[1][j] = 0.5f * (f0 - f2); G[2][j] = f1 - p;
        }
        #pragma unroll
        for (int i = 0; i < 3; i++) {
            float p = 0.5f * (G[i][0] + G[i][2]);
            sA[w * 9 + i * 3 + 0] = p;
            sA[w * 9 + i * 3 + 1] = 0.5f * (G[i][0] - G[i][2]);
            sA[w * 9 + i * 3 + 2] = G[i][1] - p;
        }
    }
}

// ---------------------------------------------------------------------------
// Per-patch measurement: 4 fast sincos + 32 FMA
// ---------------------------------------------------------------------------
__device__ __forceinline__ float4 measure4(float a0, float a1, float a2, float a3,
                                           const float* __restrict__ A) {
    float c0, s0, c1, s1, c2, s2, c3, s3;
    __sincosf(a0, &s0, &c0);
    __sincosf(a1, &s1, &c1);
    __sincosf(a2, &s2, &c2);
    __sincosf(a3, &s3, &c3);
    float4 e;
    {
        const float* B = A;
        float t0 = fmaf(B[2], s1, fmaf(B[1], c1, B[0]));
        float t1 = fmaf(B[5], s1, fmaf(B[4], c1, B[3]));
        float t2 = fmaf(B[8], s1, fmaf(B[7], c1, B[6]));
        e.x = fmaf(s0, t2, fmaf(c0, t1, t0));
    }
    {
        const float* B = A + 9;
        float t0 = fmaf(B[2], s1, fmaf(B[1], c1, B[0]));
        float t1 = fmaf(B[5], s1, fmaf(B[4], c1, B[3]));
        float t2 = fmaf(B[8], s1, fmaf(B[7], c1, B[6]));
        e.y = fmaf(s0, t2, fmaf(c0, t1, t0));
    }
    {
        const float* B = A + 18;
        float t0 = fmaf(B[2], s3, fmaf(B[1], c3, B[0]));
        float t1 = fmaf(B[5], s3, fmaf(B[4], c3, B[3]));
        float t2 = fmaf(B[8], s3, fmaf(B[7], c3, B[6]));
        e.z = fmaf(s2, t2, fmaf(c2, t1, t0));
    }
    {
        const float* B = A + 27;
        float t0 = fmaf(B[2], s3, fmaf(B[1], c3, B[0]));
        float t1 = fmaf(B[5], s3, fmaf(B[4], c3, B[3]));
        float t2 = fmaf(B[8], s3, fmaf(B[7], c3, B[6]));
        e.w = fmaf(s2, t2, fmaf(c2, t1, t0));
    }
    return e;
}

// ---------------------------------------------------------------------------
// K1: coefficients (in-block) + sample-0 measure -> adjacency -> W2 fold.
// One block per m (196 blocks), 256 threads. Block 0 also publishes g_A.
// ---------------------------------------------------------------------------
__global__ void __launch_bounds__(256) fold_kernel(const float* __restrict__ x,
                                                   const float* __restrict__ qp,
                                                   const float* __restrict__ W) {
    __shared__ float sF[36];
    __shared__ float sA[36];
    __shared__ float v[196][4];
    __shared__ float nrm[196];
    __shared__ float adjc[196];

    const int m   = blockIdx.x;
    const int tid = threadIdx.x;

    build_A_phase1(qp, sF, tid);
    __syncthreads();
    build_A_phase2(sF, sA, tid);
    __syncthreads();

    if (blockIdx.x == 0 && tid < 36) g_A[tid] = sA[tid];

    if (tid < 196) {
        int pi = tid / 14, pj = tid - pi * 14;
        const float* xb = x + (2 * pi) * 28 + 2 * pj;
        float4 e = measure4(xb[0], xb[1], xb[28], xb[29], sA);
        v[tid][0] = e.x; v[tid][1] = e.y; v[tid][2] = e.z; v[tid][3] = e.w;
        nrm[tid] = sqrtf(e.x * e.x + e.y * e.y + e.z * e.z + e.w * e.w);
    }
    __syncthreads();

    if (tid < 196) {
        float dot = v[tid][0] * v[m][0] + v[tid][1] * v[m][1] +
                    v[tid][2] * v[m][2] + v[tid][3] * v[m][3];
        float sim = dot / (nrm[tid] * nrm[m] + 1e-12f);
        adjc[tid] = (sim >= 0.9f) ? 1.0f : ((sim >= 0.5f) ? 0.5f : 0.0f);
    }
    __syncthreads();

    // W2[k][4m+d] = sum_n adj[n,m] * W[k][4n+d]; 40 outputs, 5 per warp,
    // lane-strided dot + shfl reduce.
    const int warp = tid >> 5;
    const int lane = tid & 31;
    #pragma unroll
    for (int q = 0; q < 5; q++) {
        const int o = warp * 5 + q;
        const int k = o >> 2, d = o & 3;
        float s = 0.0f;
        #pragma unroll
        for (int n = lane; n < 196; n += 32)
            s = fmaf(adjc[n], __ldg(&W[k * 784 + 4 * n + d]), s);
        #pragma unroll
        for (int off = 16; off; off >>= 1)
            s += __shfl_xor_sync(0xFFFFFFFFu, s, off);
        if (lane == 0)
            g_W2[k * 784 + 4 * m + d] = s;
    }
}

// ---------------------------------------------------------------------------
// K2: fused main. One warp = TWO batch samples (W2 loads reused across both).
// 16 samples/block, 256 blocks. Lane 0 / lane 1 finalize the two samples.
// ---------------------------------------------------------------------------
#define SPB 16   // samples per block
__global__ void __launch_bounds__(256) main_kernel(const float* __restrict__ x,
                                                   const float* __restrict__ bias,
                                                   float* __restrict__ out) {
    __shared__ float sx[SPB * 784];   // 50176 B
    __shared__ float sA[36];

    const int tid  = threadIdx.x;
    const int warp = tid >> 5;
    const int lane = tid & 31;

    // cooperative vectorized stage of 16 sample rows
    {
        const float4* xin = (const float4*)(x + (size_t)blockIdx.x * SPB * 784);
        float4* sx4 = (float4*)sx;
        #pragma unroll
        for (int i = tid; i < SPB * 196; i += 256) sx4[i] = xin[i];
    }
    if (tid < 36) sA[tid] = g_A[tid];
    __syncthreads();

    float A[36];
    #pragma unroll
    for (int i = 0; i < 36; i++) A[i] = sA[i];

    const float* rowA = sx + (2 * warp) * 784;
    const float* rowB = rowA + 784;
    const float4* W2v = (const float4*)g_W2;   // [10][196]

    float accA[10], accB[10];
    #pragma unroll
    for (int k = 0; k < 10; k++) { accA[k] = 0.0f; accB[k] = 0.0f; }

    int m  = lane;
    int pi = lane / 14;
    int pj = lane - pi * 14;
    #pragma unroll
    for (int it = 0; it < 7; it++) {
        if (it < 6 || m < 196) {
            const int off = pi * 56 + 2 * pj;
            const float2 tA = *(const float2*)(rowA + off);
            const float2 bA = *(const float2*)(rowA + off + 28);
            const float2 tB = *(const float2*)(rowB + off);
            const float2 bB = *(const float2*)(rowB + off + 28);
            float4 eA = measure4(tA.x, tA.y, bA.x, bA.y, A);
            float4 eB = measure4(tB.x, tB.y, bB.x, bB.y, A);
            #pragma unroll
            for (int k = 0; k < 10; k++) {
                float4 w4 = __ldg(W2v + k * 196 + m);
                accA[k] = fmaf(eA.x, w4.x, fmaf(eA.y, w4.y,
                          fmaf(eA.z, w4.z, fmaf(eA.w, w4.w, accA[k]))));
                accB[k] = fmaf(eB.x, w4.x, fmaf(eB.y, w4.y,
                          fmaf(eB.z, w4.z, fmaf(eB.w, w4.w, accB[k]))));
            }
        }
        m += 32;
        pj += 4; pi += 2;
        if (pj >= 14) { pj -= 14; pi += 1; }
    }

    #pragma unroll
    for (int k = 0; k < 10; k++) {
        #pragma unroll
        for (int off = 16; off; off >>= 1) {
            accA[k] += __shfl_xor_sync(0xFFFFFFFFu, accA[k], off);
            accB[k] += __shfl_xor_sync(0xFFFFFFFFu, accB[k], off);
        }
    }

    if (lane < 2) {
        const int samp = blockIdx.x * SPB + 2 * warp + lane;
        float logit[10], mx2 = -1e30f;
        #pragma unroll
        for (int k = 0; k < 10; k++) {
            float a = (lane == 0) ? accA[k] : accB[k];
            logit[k] = a + __ldg(&bias[k]);
            mx2 = fmaxf(mx2, logit[k]);
        }
        float sum = 0.0f;
        #pragma unroll
        for (int k = 0; k < 10; k++) sum += __expf(logit[k] - mx2);
        float lse = mx2 + __logf(sum);
        #pragma unroll
        for (int k = 0; k < 10; k++)
            out[samp * 10 + k] = logit[k] - lse;
    }
}

extern "C" void kernel_launch(void* const* d_in, const int* in_sizes, int n_in,
                              void* d_out, int out_size) {
    const float* x  = (const float*)d_in[0];
    const float* qp = (const float*)d_in[1];
    const float* W  = (const float*)d_in[2];
    const float* b  = (const float*)d_in[3];
    float* out = (float*)d_out;

    fold_kernel<<<196, 256>>>(x, qp, W);
    main_kernel<<<BATCH / SPB, 256>>>(x, b, out);
}

// round 9
// speedup vs baseline: 1.2966x; 1.0138x over previous
#include <cuda_runtime.h>
#include <math.h>

#define BATCH  4096
#define NPATCH 196

// Folded head weights as float4: g_W2[(k*196+m)*4 + d] = W2[k][4m+d]
__device__ __align__(16) float g_W2[10 * 784];
// Bilinear coefficient matrices (flattened [4][9]); e_w = u(a)^T A_w u(a'),
// u = (1, cos a, sin a). w=0,1 over (a0,a1); w=2,3 over (a2,a3).
__device__ float g_A[36];

// ---------------------------------------------------------------------------
// Per-thread probe: given half-angle amplitudes (chi,shi),(chj,shj) for the
// two encoder wires of a subsystem, run the fixed 2-qubit circuit twice
// (subsystem A: RX(q0),RY(q1),CNOT,RY(q4); subsystem B: RZ(q2),RX(q3),CNOT,RZ(q5))
// and return the 4 Pauli-Z probe values F[w].
// ---------------------------------------------------------------------------
__device__ __forceinline__ void probe_circuit(float chi, float shi, float chj, float shj,
                                              const float* qc, const float* qs,
                                              float F[4]) {
    // ---- subsystem A: wires 0 (high bit), 1 (low bit) ----
    {
        float re[4], im[4];
        re[0] = chi * chj; re[1] = chi * shj;
        re[2] = shi * chj; re[3] = shi * shj;
        im[0] = im[1] = im[2] = im[3] = 0.0f;
        // RX(q0) on high bit: pairs (0,2),(1,3)
        #pragma unroll
        for (int b = 0; b < 2; b++) {
            int a = b, t = b | 2;
            float ra = re[a], ia = im[a], rb = re[t], ib = im[t];
            float c = qc[0], s = qs[0];
            re[a] = c * ra + s * ib;  im[a] = c * ia - s * rb;
            re[t] = s * ia + c * rb;  im[t] = -s * ra + c * ib;
        }
        // RY(q1) on low bit: pairs (0,1),(2,3)
        #pragma unroll
        for (int b = 0; b < 4; b += 2) {
            int a = b, t = b | 1;
            float ra = re[a], ia = im[a], rb = re[t], ib = im[t];
            float c = qc[1], s = qs[1];
            re[a] = c * ra - s * rb;  im[a] = c * ia - s * ib;
            re[t] = s * ra + c * rb;  im[t] = s * ia + c * ib;
        }
        // CNOT(high->low): swap 2<->3
        { float t0 = re[2]; re[2] = re[3]; re[3] = t0;
          float t1 = im[2]; im[2] = im[3]; im[3] = t1; }
        // RY(q4) on high bit
        #pragma unroll
        for (int b = 0; b < 2; b++) {
            int a = b, t = b | 2;
            float ra = re[a], ia = im[a], rb = re[t], ib = im[t];
            float c = qc[4], s = qs[4];
            re[a] = c * ra - s * rb;  im[a] = c * ia - s * ib;
            re[t] = s * ra + c * rb;  im[t] = s * ia + c * ib;
        }
        float p0 = re[0]*re[0]+im[0]*im[0], p1 = re[1]*re[1]+im[1]*im[1];
        float p2 = re[2]*re[2]+im[2]*im[2], p3 = re[3]*re[3]+im[3]*im[3];
        F[0] = p0 + p1 - p2 - p3;
        F[1] = p0 - p1 + p2 - p3;
    }
    // ---- subsystem B: wires 2 (high bit), 3 (low bit) ----
    {
        float re[4], im[4];
        re[0] = chi * chj; re[1] = chi * shj;
        re[2] = shi * chj; re[3] = shi * shj;
        im[0] = im[1] = im[2] = im[3] = 0.0f;
        // RZ(q2) on high
        #pragma unroll
        for (int a = 0; a < 4; a++) {
            float c = qc[2], s = (a & 2) ? -qs[2] : qs[2];
            float ra = re[a], ia = im[a];
            re[a] = c * ra + s * ia;  im[a] = c * ia - s * ra;
        }
        // RX(q3) on low bit
        #pragma unroll
        for (int b = 0; b < 4; b += 2) {
            int a = b, t = b | 1;
            float ra = re[a], ia = im[a], rb = re[t], ib = im[t];
            float c = qc[3], s = qs[3];
            re[a] = c * ra + s * ib;  im[a] = c * ia - s * rb;
            re[t] = s * ia + c * rb;  im[t] = -s * ra + c * ib;
        }
        // CNOT(high->low): swap 2<->3
        { float t0 = re[2]; re[2] = re[3]; re[3] = t0;
          float t1 = im[2]; im[2] = im[3]; im[3] = t1; }
        // RZ(q5) on low
        #pragma unroll
        for (int a = 0; a < 4; a++) {
            float c = qc[5], s = (a & 1) ? -qs[5] : qs[5];
            float ra = re[a], ia = im[a];
            re[a] = c * ra + s * ia;  im[a] = c * ia - s * ra;
        }
        float p0 = re[0]*re[0]+im[0]*im[0], p1 = re[1]*re[1]+im[1]*im[1];
        float p2 = re[2]*re[2]+im[2]*im[2], p3 = re[3]*re[3]+im[3]*im[3];
        F[2] = p0 + p1 - p2 - p3;
        F[3] = p0 - p1 + p2 - p3;
    }
}

// Cooperative coefficient build: threads 0..8 probe, threads 0..3 convert.
// Leaves sA[36] populated. Requires one __syncthreads between phases (done
// by the caller pattern below).
__device__ __forceinline__ void build_A_phase1(const float* __restrict__ qp,
                                               float* sF /*[4*9]*/, int tid) {
    if (tid < 9) {
        float qc[6], qs[6];
        #pragma unroll
        for (int k = 0; k < 6; k++) sincosf(0.5f * __ldg(&qp[k]), &qs[k], &qc[k]);
        const float chp[3] = {1.0f, 0.7071067811865476f, 0.0f};
        const float shp[3] = {0.0f, 0.7071067811865476f, 1.0f};
        int i = tid / 3, j = tid - 3 * i;
        float F[4];
        probe_circuit(chp[i], shp[i], chp[j], shp[j], qc, qs, F);
        #pragma unroll
        for (int w = 0; w < 4; w++) sF[w * 9 + tid] = F[w];
    }
}

__device__ __forceinline__ void build_A_phase2(const float* sF, float* sA, int tid) {
    if (tid < 4) {
        const int w = tid;
        float G[3][3];
        #pragma unroll
        for (int j = 0; j < 3; j++) {
            float f0 = sF[w * 9 + 0 * 3 + j];
            float f1 = sF[w * 9 + 1 * 3 + j];
            float f2 = sF[w * 9 + 2 * 3 + j];
            float p = 0.5f * (f0 + f2);
            G[0][j] = p; G[1][j] = 0.5f * (f0 - f2); G[2][j] = f1 - p;
        }
        #pragma unroll
        for (int i = 0; i < 3; i++) {
            float p = 0.5f * (G[i][0] + G[i][2]);
            sA[w * 9 + i * 3 + 0] = p;
            sA[w * 9 + i * 3 + 1] = 0.5f * (G[i][0] - G[i][2]);
            sA[w * 9 + i * 3 + 2] = G[i][1] - p;
        }
    }
}

// ---------------------------------------------------------------------------
// Per-patch measurement: 4 fast sincos + 32 FMA
// ---------------------------------------------------------------------------
__device__ __forceinline__ float4 measure4(float a0, float a1, float a2, float a3,
                                           const float* __restrict__ A) {
    float c0, s0, c1, s1, c2, s2, c3, s3;
    __sincosf(a0, &s0, &c0);
    __sincosf(a1, &s1, &c1);
    __sincosf(a2, &s2, &c2);
    __sincosf(a3, &s3, &c3);
    float4 e;
    {
        const float* B = A;
        float t0 = fmaf(B[2], s1, fmaf(B[1], c1, B[0]));
        float t1 = fmaf(B[5], s1, fmaf(B[4], c1, B[3]));
        float t2 = fmaf(B[8], s1, fmaf(B[7], c1, B[6]));
        e.x = fmaf(s0, t2, fmaf(c0, t1, t0));
    }
    {
        const float* B = A + 9;
        float t0 = fmaf(B[2], s1, fmaf(B[1], c1, B[0]));
        float t1 = fmaf(B[5], s1, fmaf(B[4], c1, B[3]));
        float t2 = fmaf(B[8], s1, fmaf(B[7], c1, B[6]));
        e.y = fmaf(s0, t2, fmaf(c0, t1, t0));
    }
    {
        const float* B = A + 18;
        float t0 = fmaf(B[2], s3, fmaf(B[1], c3, B[0]));
        float t1 = fmaf(B[5], s3, fmaf(B[4], c3, B[3]));
        float t2 = fmaf(B[8], s3, fmaf(B[7], c3, B[6]));
        e.z = fmaf(s2, t2, fmaf(c2, t1, t0));
    }
    {
        const float* B = A + 27;
        float t0 = fmaf(B[2], s3, fmaf(B[1], c3, B[0]));
        float t1 = fmaf(B[5], s3, fmaf(B[4], c3, B[3]));
        float t2 = fmaf(B[8], s3, fmaf(B[7], c3, B[6]));
        e.w = fmaf(s2, t2, fmaf(c2, t1, t0));
    }
    return e;
}

// ---------------------------------------------------------------------------
// K1: coefficients (in-block) + sample-0 measure -> adjacency -> W2 fold.
// One block per m (196 blocks), 256 threads. Block 0 also publishes g_A.
// ---------------------------------------------------------------------------
__global__ void __launch_bounds__(256) fold_kernel(const float* __restrict__ x,
                                                   const float* __restrict__ qp,
                                                   const float* __restrict__ W) {
    __shared__ float sF[36];
    __shared__ float sA[36];
    __shared__ float v[196][4];
    __shared__ float nrm[196];
    __shared__ float adjc[196];

    const int m   = blockIdx.x;
    const int tid = threadIdx.x;

    build_A_phase1(qp, sF, tid);
    __syncthreads();
    build_A_phase2(sF, sA, tid);
    __syncthreads();

    if (blockIdx.x == 0 && tid < 36) g_A[tid] = sA[tid];

    if (tid < 196) {
        int pi = tid / 14, pj = tid - pi * 14;
        const float* xb = x + (2 * pi) * 28 + 2 * pj;
        float4 e = measure4(xb[0], xb[1], xb[28], xb[29], sA);
        v[tid][0] = e.x; v[tid][1] = e.y; v[tid][2] = e.z; v[tid][3] = e.w;
        nrm[tid] = sqrtf(e.x * e.x + e.y * e.y + e.z * e.z + e.w * e.w);
    }
    __syncthreads();

    if (tid < 196) {
        float dot = v[tid][0] * v[m][0] + v[tid][1] * v[m][1] +
                    v[tid][2] * v[m][2] + v[tid][3] * v[m][3];
        float sim = dot / (nrm[tid] * nrm[m] + 1e-12f);
        adjc[tid] = (sim >= 0.9f) ? 1.0f : ((sim >= 0.5f) ? 0.5f : 0.0f);
    }
    __syncthreads();

    // W2[k][4m+d] = sum_n adj[n,m] * W[k][4n+d]; 40 outputs, 5 per warp,
    // lane-strided dot + shfl reduce.
    const int warp = tid >> 5;
    const int lane = tid & 31;
    #pragma unroll
    for (int q = 0; q < 5; q++) {
        const int o = warp * 5 + q;
        const int k = o >> 2, d = o & 3;
        float s = 0.0f;
        #pragma unroll
        for (int n = lane; n < 196; n += 32)
            s = fmaf(adjc[n], __ldg(&W[k * 784 + 4 * n + d]), s);
        #pragma unroll
        for (int off = 16; off; off >>= 1)
            s += __shfl_xor_sync(0xFFFFFFFFu, s, off);
        if (lane == 0)
            g_W2[k * 784 + 4 * m + d] = s;
    }
}

// ---------------------------------------------------------------------------
// K2: fused main. One warp = TWO batch samples (W2 loads reused across both).
// 16 samples/block, 256 blocks. Lane 0 / lane 1 finalize the two samples.
// ---------------------------------------------------------------------------
#define SPB 16   // samples per block
__global__ void __launch_bounds__(256) main_kernel(const float* __restrict__ x,
                                                   const float* __restrict__ bias,
                                                   float* __restrict__ out) {
    __shared__ float sx[SPB * 784];   // 50176 B
    __shared__ float sA[36];

    const int tid  = threadIdx.x;
    const int warp = tid >> 5;
    const int lane = tid & 31;

    // cooperative vectorized stage of 16 sample rows
    {
        const float4* xin = (const float4*)(x + (size_t)blockIdx.x * SPB * 784);
        float4* sx4 = (float4*)sx;
        #pragma unroll
        for (int i = tid; i < SPB * 196; i += 256) sx4[i] = xin[i];
    }
    if (tid < 36) sA[tid] = g_A[tid];
    __syncthreads();

    float A[36];
    #pragma unroll
    for (int i = 0; i < 36; i++) A[i] = sA[i];

    const float* rowA = sx + (2 * warp) * 784;
    const float* rowB = rowA + 784;
    const float4* W2v = (const float4*)g_W2;   // [10][196]

    float accA[10], accB[10];
    #pragma unroll
    for (int k = 0; k < 10; k++) { accA[k] = 0.0f; accB[k] = 0.0f; }

    int m  = lane;
    int pi = lane / 14;
    int pj = lane - pi * 14;
    #pragma unroll
    for (int it = 0; it < 7; it++) {
        if (it < 6 || m < 196) {
            const int off = pi * 56 + 2 * pj;
            const float2 tA = *(const float2*)(rowA + off);
            const float2 bA = *(const float2*)(rowA + off + 28);
            const float2 tB = *(const float2*)(rowB + off);
            const float2 bB = *(const float2*)(rowB + off + 28);
            float4 eA = measure4(tA.x, tA.y, bA.x, bA.y, A);
            float4 eB = measure4(tB.x, tB.y, bB.x, bB.y, A);
            #pragma unroll
            for (int k = 0; k < 10; k++) {
                float4 w4 = __ldg(W2v + k * 196 + m);
                accA[k] = fmaf(eA.x, w4.x, fmaf(eA.y, w4.y,
                          fmaf(eA.z, w4.z, fmaf(eA.w, w4.w, accA[k]))));
                accB[k] = fmaf(eB.x, w4.x, fmaf(eB.y, w4.y,
                          fmaf(eB.z, w4.z, fmaf(eB.w, w4.w, accB[k]))));
            }
        }
        m += 32;
        pj += 4; pi += 2;
        if (pj >= 14) { pj -= 14; pi += 1; }
    }

    #pragma unroll
    for (int k = 0; k < 10; k++) {
        #pragma unroll
        for (int off = 16; off; off >>= 1) {
            accA[k] += __shfl_xor_sync(0xFFFFFFFFu, accA[k], off);
            accB[k] += __shfl_xor_sync(0xFFFFFFFFu, accB[k], off);
        }
    }

    if (lane < 2) {
        const int samp = blockIdx.x * SPB + 2 * warp + lane;
        float logit[10], mx2 = -1e30f;
        #pragma unroll
        for (int k = 0; k < 10; k++) {
            float a = (lane == 0) ? accA[k] : accB[k];
            logit[k] = a + __ldg(&bias[k]);
            mx2 = fmaxf(mx2, logit[k]);
        }
        float sum = 0.0f;
        #pragma unroll
        for (int k = 0; k < 10; k++) sum += __expf(logit[k] - mx2);
        float lse = mx2 + __logf(sum);
        #pragma unroll
        for (int k = 0; k < 10; k++)
            out[samp * 10 + k] = logit[k] - lse;
    }
}

extern "C" void kernel_launch(void* const* d_in, const int* in_sizes, int n_in,
                              void* d_out, int out_size) {
    const float* x  = (const float*)d_in[0];
    const float* qp = (const float*)d_in[1];
    const float* W  = (const float*)d_in[2];
    const float* b  = (const float*)d_in[3];
    float* out = (float*)d_out;

    fold_kernel<<<196, 256>>>(x, qp, W);
    main_kernel<<<BATCH / SPB, 256>>>(x, b, out);
}